// round 5
// baseline (speedup 1.0000x reference)
#include <cuda_runtime.h>

// Cost-volume correlation, MAX_DISP=4 (81 displacements), kernel_size=1.
// out[b, dy*9+dx, y, x] = (1/C) * sum_c in1[b,c,y,x] * in2[b,c,y+dy-4,x+dx-4]
// (zero padded outside [0,H)x[0,W)).
//
// Strategy:
//  - block (32,8): tile of 64 x-pixels (2 per thread, packed in f32x2) x 8 y-rows.
//  - 81 packed f32x2 accumulators per thread (each covers pixels x and x+1).
//  - per channel: in2 halo tile (16 rows x 72 cols) staged in smem,
//    double-buffered via registers (LDG next channel overlapped with compute).
//  - inner: per dy, 5 conflict-free LDS.64 (10-float window), 9 fma.rn.f32x2
//    (even-dx pairs direct, odd-dx pairs repacked from register halves).

typedef unsigned long long u64;

__device__ __forceinline__ u64 pk(float lo, float hi) {
    u64 r; asm("mov.b64 %0, {%1,%2};" : "=l"(r) : "f"(lo), "f"(hi)); return r;
}
__device__ __forceinline__ void upk(u64 v, float &lo, float &hi) {
    asm("mov.b64 {%0,%1}, %2;" : "=f"(lo), "=f"(hi) : "l"(v));
}
__device__ __forceinline__ void fma2(u64 &d, u64 a, u64 b) {
    asm("fma.rn.f32x2 %0, %1, %2, %0;" : "+l"(d) : "l"(a), "l"(b));
}

#define CC 128
#define HH 128
#define WW 128
#define NDISP 81
#define TILE_R 16            // 8 y-rows + 2*4 halo
#define TILE_C 72            // 64 x-pixels + 2*4 halo
#define TILE_N (TILE_R * TILE_C)   // 1152
#define HW (HH * WW)

__global__ __launch_bounds__(256, 1)
void corr_kernel(const float* __restrict__ in1,
                 const float* __restrict__ in2,
                 float* __restrict__ out)
{
    __shared__ float sm[2][TILE_N];

    const int tx  = threadIdx.x;            // 0..31
    const int ty  = threadIdx.y;            // 0..7
    const int tid = ty * 32 + tx;           // 0..255
    const int x0  = blockIdx.x * 64;
    const int y0  = blockIdx.y * 8;
    const int b   = blockIdx.z;

    const int y = y0 + ty;
    const int x = x0 + tx * 2;              // this thread: pixels x, x+1

    const float* i1 = in1 + ((b * CC) * HH + y) * WW + x;
    const float* i2 = in2 + (b * CC) * HW;

    u64 acc[NDISP];
#pragma unroll
    for (int i = 0; i < NDISP; i++) acc[i] = 0ull;

    // Precompute (c-independent) tile-load offsets + predicates.
    int  off[5];
    bool ok[5];
#pragma unroll
    for (int k = 0; k < 5; k++) {
        int i  = tid + k * 256;
        int r  = i / TILE_C;
        int cl = i - r * TILE_C;
        int gy = y0 - 4 + r;
        int gx = x0 - 4 + cl;
        ok[k]  = (i < TILE_N) && (gy >= 0) && (gy < HH) && (gx >= 0) && (gx < WW);
        off[k] = gy * WW + gx;
    }

    // Prologue: load channel 0.
    float v[5];
#pragma unroll
    for (int k = 0; k < 5; k++) v[k] = ok[k] ? __ldg(i2 + off[k]) : 0.0f;
    float a0 = i1[0];
    float a1 = i1[1];
#pragma unroll
    for (int k = 0; k < 5; k++) {
        int i = tid + k * 256;
        if (i < TILE_N) sm[0][i] = v[k];
    }
    __syncthreads();

    int cur = 0;
    for (int c = 0; c < CC; c++) {
        // Prefetch next channel into registers (hides gmem latency under FMAs).
        float vn[5];
        float a0n = 0.0f, a1n = 0.0f;
        const bool more = (c + 1 < CC);
        if (more) {
            const float* p = i2 + (c + 1) * HW;
#pragma unroll
            for (int k = 0; k < 5; k++) vn[k] = ok[k] ? __ldg(p + off[k]) : 0.0f;
            a0n = i1[(c + 1) * HW];
            a1n = i1[(c + 1) * HW + 1];
        } else {
#pragma unroll
            for (int k = 0; k < 5; k++) vn[k] = 0.0f;
        }

        const u64 a2 = pk(a0, a1);
        const float* base = &sm[cur][ty * TILE_C + tx * 2];   // window col 0 = x-4

#pragma unroll
        for (int dy = 0; dy < 9; dy++) {
            const float2* rp = reinterpret_cast<const float2*>(base + dy * TILE_C);
            float2 p0 = rp[0];
            float2 p1 = rp[1];
            float2 p2 = rp[2];
            float2 p3 = rp[3];
            float2 p4 = rp[4];
            const int w0 = dy * 9;
            // even dx: aligned pairs straight from LDS.64 results
            fma2(acc[w0 + 0], a2, pk(p0.x, p0.y));
            fma2(acc[w0 + 2], a2, pk(p1.x, p1.y));
            fma2(acc[w0 + 4], a2, pk(p2.x, p2.y));
            fma2(acc[w0 + 6], a2, pk(p3.x, p3.y));
            fma2(acc[w0 + 8], a2, pk(p4.x, p4.y));
            // odd dx: repacked from register halves
            fma2(acc[w0 + 1], a2, pk(p0.y, p1.x));
            fma2(acc[w0 + 3], a2, pk(p1.y, p2.x));
            fma2(acc[w0 + 5], a2, pk(p2.y, p3.x));
            fma2(acc[w0 + 7], a2, pk(p3.y, p4.x));
        }

        if (more) {
#pragma unroll
            for (int k = 0; k < 5; k++) {
                int i = tid + k * 256;
                if (i < TILE_N) sm[cur ^ 1][i] = vn[k];
            }
            a0 = a0n;
            a1 = a1n;
        }
        __syncthreads();
        cur ^= 1;
    }

    // Epilogue: mean over C, vectorized float2 stores (x is even -> 8B aligned).
    const float s = 1.0f / (float)CC;
    float* ob = out + ((b * NDISP) * HH + y) * WW + x;
#pragma unroll
    for (int w = 0; w < NDISP; w++) {
        float lo, hi;
        upk(acc[w], lo, hi);
        float2 o;
        o.x = lo * s;
        o.y = hi * s;
        *reinterpret_cast<float2*>(ob + w * HW) = o;
    }
}

extern "C" void kernel_launch(void* const* d_in, const int* in_sizes, int n_in,
                              void* d_out, int out_size)
{
    const float* in1 = (const float*)d_in[0];
    const float* in2 = (const float*)d_in[1];
    float* out = (float*)d_out;

    const int B = in_sizes[0] / (CC * HH * WW);   // 8 for this problem

    dim3 block(32, 8);
    dim3 grid(WW / 64, HH / 8, B);
    corr_kernel<<<grid, block>>>(in1, in2, out);
}